// round 12
// baseline (speedup 1.0000x reference)
#include <cuda_runtime.h>
#include <cuda_fp16.h>
#include <cstdint>

#define B_  32
#define HW  3136
#define C_  256
#define F_  256
#define NK  4
#define PER_B (2304*256)
#define NT  532            // 28(h) x 19(w) F(2x3) tiles per sample
#define NTP 544            // padded (17 blocks of 32); pad stays zero
#define XI  20             // 4(h) x 5(w)
#define PH  72             // gemm smem pitch in halves (64 + 8 pad)
#define ASTG (128*PH*2)    // 18432 B per A stage
#define BSTG (32*PH*2)     // 4608 B per B stage
#define SMEM_GEMM (3*ASTG + 3*BSTG)   // 69120 B

// ---------------- scratch ----------------
__device__ float g_part[B_ * 16 * C_];
__device__ float g_attn[B_ * NK];
__device__ float g_beff[B_ * F_];
__device__ __half g_U[(size_t)B_ * XI * F_ * C_];    // [b][xi][f][c]
__device__ __half g_V[(size_t)B_ * XI * NTP * C_];   // [b][xi][tile][c] (pad zero)

// ============ 1) Input transform F(2x3) + fused GAP partial ============
__global__ void __launch_bounds__(256)
itrans_kernel(const float* __restrict__ x) {
    __shared__ float sx[16 * 17 * 32];
    __shared__ float red[8][32];
    const int b  = blockIdx.z;
    const int c0 = blockIdx.y * 32;
    const int bi = blockIdx.x >> 2, bj = blockIdx.x & 3;
    const int t  = threadIdx.x;

    const float* xb = x + (size_t)b * HW * C_ + c0;
    const int r0g = 14 * bi - 1, c0g = 15 * bj - 1;
    #pragma unroll
    for (int p = 0; p < 9; ++p) {
        int u = p * 256 + t;
        if (u < 2176) {
            int px = u >> 3, cu = u & 7;
            int rp = px / 17, cp = px - rp * 17;
            int ih = r0g + rp, iw = c0g + cp;
            float4 v = make_float4(0.f, 0.f, 0.f, 0.f);
            if ((unsigned)ih < 56u && (unsigned)iw < 56u)
                v = *(const float4*)(xb + (size_t)(ih * 56 + iw) * C_ + cu * 4);
            *(float4*)(sx + px * 32 + cu * 4) = v;
        }
    }
    __syncthreads();

    {
        const int part = t >> 5, cl = t & 31;
        float ps = 0.f;
        for (int i = part; i < 210; i += 8) {
            int rr = i / 15, cc = i - (i / 15) * 15;
            if (15 * bj + cc < 56)
                ps += sx[((rr + 1) * 17 + (cc + 1)) * 32 + cl];
        }
        red[part][cl] = ps;
    }
    __syncthreads();
    if (t < 32) {
        float s = 0.f;
        #pragma unroll
        for (int r = 0; r < 8; ++r) s += red[r][t];
        g_part[(b * 16 + blockIdx.x) * C_ + c0 + t] = s;
    }

    for (int item = t; item < 560; item += 256) {
        const int tile = item >> 4, cp2 = item & 15;
        const int lti = tile / 5, ltj = tile - (tile / 5) * 5;
        const int gti = 7 * bi + lti, gtj = 5 * bj + ltj;
        if (gtj >= 19) continue;
        const int cc = cp2 * 2;

        float2 d[4][5];
        #pragma unroll
        for (int i = 0; i < 4; ++i)
            #pragma unroll
            for (int j = 0; j < 5; ++j)
                d[i][j] = *(const float2*)(sx + ((2 * lti + i) * 17 + 3 * ltj + j) * 32 + cc);

        float2 T[4][5];
        #pragma unroll
        for (int j = 0; j < 5; ++j) {
            T[0][j] = make_float2(d[0][j].x - d[2][j].x, d[0][j].y - d[2][j].y);
            T[1][j] = make_float2(d[1][j].x + d[2][j].x, d[1][j].y + d[2][j].y);
            T[2][j] = make_float2(d[2][j].x - d[1][j].x, d[2][j].y - d[1][j].y);
            T[3][j] = make_float2(d[1][j].x - d[3][j].x, d[1][j].y - d[3][j].y);
        }

        const int tg = gti * 19 + gtj;
        __half* Vb = g_V + ((size_t)(b * XI) * NTP + tg) * C_ + c0 + cc;
        #pragma unroll
        for (int nu = 0; nu < 4; ++nu) {
            float2 t0 = T[nu][0], t1 = T[nu][1], t2 = T[nu][2], t3 = T[nu][3], t4 = T[nu][4];
            float2 V[5];
            V[0] = make_float2(4.f*t0.x - 5.f*t2.x + t4.x,      4.f*t0.y - 5.f*t2.y + t4.y);
            V[1] = make_float2(-4.f*t1.x - 4.f*t2.x + t3.x + t4.x, -4.f*t1.y - 4.f*t2.y + t3.y + t4.y);
            V[2] = make_float2(4.f*t1.x - 4.f*t2.x - t3.x + t4.x,  4.f*t1.y - 4.f*t2.y - t3.y + t4.y);
            V[3] = make_float2(-2.f*t1.x - t2.x + 2.f*t3.x + t4.x, -2.f*t1.y - t2.y + 2.f*t3.y + t4.y);
            V[4] = make_float2(2.f*t1.x - t2.x - 2.f*t3.x + t4.x,  2.f*t1.y - t2.y - 2.f*t3.y + t4.y);
            #pragma unroll
            for (int mu = 0; mu < 5; ++mu) {
                __half2 h = __floats2half2_rn(V[mu].x, V[mu].y);
                *(uint32_t*)(Vb + (size_t)(nu * 5 + mu) * NTP * C_) = *(uint32_t*)&h;
            }
        }
    }
}

// ============ 2) Fused: GAP final + router MLP + softmax + beff ============
__global__ void router_kernel(const float* __restrict__ w1, const float* __restrict__ b1,
                              const float* __restrict__ w2, const float* __restrict__ b2,
                              const float* __restrict__ biases) {
    int b = blockIdx.x, t = threadIdx.x;
    __shared__ float sp[C_];
    __shared__ float sh[64];
    __shared__ float sl[NK];
    __shared__ float sa[NK];
    float s = 0.f;
    #pragma unroll
    for (int ch = 0; ch < 16; ++ch) s += g_part[(b * 16 + ch) * C_ + t];
    sp[t] = s * (1.0f / 3136.0f);
    __syncthreads();
    if (t < 64) {
        float acc = b1[t];
        #pragma unroll 4
        for (int c = 0; c < C_; ++c) acc += sp[c] * w1[c * 64 + t];
        sh[t] = fmaxf(acc, 0.f);
    }
    __syncthreads();
    if (t < NK) {
        float lg = b2[t];
        #pragma unroll
        for (int i = 0; i < 64; ++i) lg += sh[i] * w2[i * NK + t];
        sl[t] = lg * (1.0f / 30.0f);
    }
    __syncthreads();
    if (t == 0) {
        float mx = fmaxf(fmaxf(sl[0], sl[1]), fmaxf(sl[2], sl[3]));
        float e0 = expf(sl[0] - mx), e1 = expf(sl[1] - mx);
        float e2 = expf(sl[2] - mx), e3 = expf(sl[3] - mx);
        float inv = 1.0f / (e0 + e1 + e2 + e3);
        sa[0] = e0 * inv; sa[1] = e1 * inv; sa[2] = e2 * inv; sa[3] = e3 * inv;
        g_attn[b * NK + 0] = sa[0]; g_attn[b * NK + 1] = sa[1];
        g_attn[b * NK + 2] = sa[2]; g_attn[b * NK + 3] = sa[3];
    }
    __syncthreads();
    float bs = 0.f;
    #pragma unroll
    for (int k = 0; k < NK; ++k) bs += sa[k] * biases[k * F_ + t];
    g_beff[b * F_ + t] = bs;
}

// ============ 3) Weight transform: U = Gh W Gw^T, fp16 [b][xi][f][c] ============
__global__ void __launch_bounds__(256)
wtrans_kernel(const float* __restrict__ kern) {
    __shared__ float sk[4][9][8][33];
    __shared__ float sa[B_][NK];
    const int f0 = blockIdx.x * 8;
    const int c0 = blockIdx.y * 32;
    const int t  = threadIdx.x;

    #pragma unroll
    for (int p = 0; p < 36; ++p) {
        int i  = p * 256 + t;
        int fl = i & 7, cl = (i >> 3) & 31, rs = (i >> 8) % 9, k = i / 2304;
        sk[k][rs][fl][cl] =
            kern[(size_t)k * PER_B + (size_t)rs * (C_ * F_) + (size_t)(c0 + cl) * F_ + f0 + fl];
    }
    if (t < B_ * NK) sa[t >> 2][t & 3] = g_attn[t];
    __syncthreads();

    const int fl = t >> 5, cl = t & 31;
    const float S6 = 1.f / 6.f, S24 = 1.f / 24.f;
    #pragma unroll 1
    for (int b = 0; b < B_; ++b) {
        const float a0 = sa[b][0], a1 = sa[b][1], a2 = sa[b][2], a3 = sa[b][3];
        float g[3][3];
        #pragma unroll
        for (int rs = 0; rs < 9; ++rs)
            g[rs / 3][rs % 3] = a0 * sk[0][rs][fl][cl] + a1 * sk[1][rs][fl][cl]
                              + a2 * sk[2][rs][fl][cl] + a3 * sk[3][rs][fl][cl];
        float q[4][3];
        #pragma unroll
        for (int j = 0; j < 3; ++j) {
            q[0][j] = g[0][j];
            q[1][j] = 0.5f * (g[0][j] + g[1][j] + g[2][j]);
            q[2][j] = 0.5f * (g[0][j] - g[1][j] + g[2][j]);
            q[3][j] = g[2][j];
        }
        __half* Ub = g_U + ((size_t)(b * XI) * F_ + f0 + fl) * C_ + c0 + cl;
        #pragma unroll
        for (int i = 0; i < 4; ++i) {
            float u0 = 0.25f * q[i][0];
            float u1 = -S6 * (q[i][0] + q[i][1] + q[i][2]);
            float u2 = -S6 * (q[i][0] - q[i][1] + q[i][2]);
            float u3 = S24 * (q[i][0] + 2.f * q[i][1] + 4.f * q[i][2]);
            float u4 = S24 * (q[i][0] - 2.f * q[i][1] + 4.f * q[i][2]);
            Ub[(size_t)(i * 5 + 0) * (F_ * C_)] = __float2half(u0);
            Ub[(size_t)(i * 5 + 1) * (F_ * C_)] = __float2half(u1);
            Ub[(size_t)(i * 5 + 2) * (F_ * C_)] = __float2half(u2);
            Ub[(size_t)(i * 5 + 3) * (F_ * C_)] = __float2half(u3);
            Ub[(size_t)(i * 5 + 4) * (F_ * C_)] = __float2half(u4);
        }
    }
}

// ============ 4) Fused Winograd GEMM + inverse transform ============
// CTA 128f x 32tiles x BK=64, 3-stage cp.async, 1 CTA/SM.
// 8 warps (4m x 2n): warp = 32f x 16 tiles, 16 MMAs / 12 LDSM per iter. 80 iters.
__device__ __forceinline__ void ldm_x4(uint32_t* r, uint32_t addr) {
    asm volatile("ldmatrix.sync.aligned.m8n8.x4.shared.b16 {%0,%1,%2,%3}, [%4];"
        : "=r"(r[0]), "=r"(r[1]), "=r"(r[2]), "=r"(r[3]) : "r"(addr));
}
__device__ __forceinline__ void mma_f16(float* d, const uint32_t* a, const uint32_t* bb) {
    asm volatile(
        "mma.sync.aligned.m16n8k16.row.col.f32.f16.f16.f32 "
        "{%0,%1,%2,%3},{%4,%5,%6,%7},{%8,%9},{%0,%1,%2,%3};"
        : "+f"(d[0]), "+f"(d[1]), "+f"(d[2]), "+f"(d[3])
        : "r"(a[0]), "r"(a[1]), "r"(a[2]), "r"(a[3]), "r"(bb[0]), "r"(bb[1]));
}
__device__ __forceinline__ void cpa16(uint32_t s, const void* g) {
    asm volatile("cp.async.ca.shared.global [%0], [%1], 16;" :: "r"(s), "l"(g) : "memory");
}

__global__ void __launch_bounds__(256, 1)
wino_gemm(float* __restrict__ out) {
    extern __shared__ __align__(16) __half dsm[];

    const int t    = threadIdx.x;
    const int lane = t & 31;
    const int warp = t >> 5;
    const int wm   = warp >> 1;          // 0..3 : 32 f each
    const int wn   = warp & 1;           // 0..1 : 16 tiles each
    const int b    = blockIdx.z;
    const int f0   = blockIdx.y * 128;
    const int t0   = blockIdx.x * 32;

    const __half* Ub = g_U + (size_t)b * XI * F_ * C_;
    const __half* Vb = g_V + (size_t)b * XI * NTP * C_;

    const uint32_t aSm = (uint32_t)__cvta_generic_to_shared(dsm);
    const uint32_t bSm = aSm + 3 * ASTG;

    // ldmatrix lane addresses (stage 0)
    const uint32_t aLm = aSm + (uint32_t)(((wm * 32 + (lane & 15)) * PH + (lane >> 4) * 8) * 2);
    const uint32_t bLm = bSm + (uint32_t)(((wn * 16 + (lane & 7) + ((lane >> 4) & 1) * 8) * PH
                                           + ((lane >> 3) & 1) * 8) * 2);
    // loaders: A 128 rows x 64 halves (1024 chunks -> 4/thread), B 32 x 64 (1/thread)
    const int arow = t >> 1;
    const int acol = (t & 1) * 32;       // halves
    const int brow = t >> 3;
    const int bcol = (t & 7) * 8;
    const uint32_t aD = aSm + (uint32_t)((arow * PH + acol) * 2);
    const uint32_t bD = bSm + (uint32_t)((brow * PH + bcol) * 2);
    const __half* gA = Ub + (size_t)(f0 + arow) * C_ + acol;
    const __half* gB = Vb + (size_t)(t0 + brow) * C_ + bcol;

    float P[2][2][4];
    float o[6][2][2][4];
    #pragma unroll
    for (int mt = 0; mt < 2; ++mt)
        #pragma unroll
        for (int nt = 0; nt < 2; ++nt)
            #pragma unroll
            for (int r = 0; r < 4; ++r) P[mt][nt][r] = 0.f;
    #pragma unroll
    for (int ij = 0; ij < 6; ++ij)
        #pragma unroll
        for (int mt = 0; mt < 2; ++mt)
            #pragma unroll
            for (int nt = 0; nt < 2; ++nt)
                #pragma unroll
                for (int r = 0; r < 4; ++r) o[ij][mt][nt][r] = 0.f;

    // prologue: stages 0,1 <- it 0,1 (xi=0, kt=0,1)
    #pragma unroll
    for (int j = 0; j < 2; ++j) {
        #pragma unroll
        for (int q = 0; q < 4; ++q)
            cpa16(aD + j * ASTG + q * 16, gA + j * 64 + q * 8);
        cpa16(bD + j * BSTG, gB + j * 64);
        asm volatile("cp.async.commit_group;" ::: "memory");
    }

    int cur = 0;
    #pragma unroll 1
    for (int it = 0; it < 80; ++it) {
        asm volatile("cp.async.wait_group 1;" ::: "memory");
        __syncthreads();

        const uint32_t soA = (uint32_t)(cur * ASTG);
        const uint32_t soB = (uint32_t)(cur * BSTG);
        uint32_t bf[4][4];
        #pragma unroll
        for (int ks = 0; ks < 4; ++ks)
            ldm_x4(bf[ks], bLm + soB + ks * 32);
        #pragma unroll
        for (int mt = 0; mt < 2; ++mt) {
            #pragma unroll
            for (int ks = 0; ks < 4; ++ks) {
                uint32_t afr[4];
                ldm_x4(afr, aLm + soA + (uint32_t)(mt * 16 * PH * 2) + ks * 32);
                mma_f16(P[mt][0], afr, &bf[ks][0]);
                mma_f16(P[mt][1], afr, &bf[ks][2]);
            }
        }

        // fold xi into inverse-transform accumulators
        if ((it & 3) == 3) {
            const int xi = it >> 2;
            const int nu = xi / 5, mu = xi - nu * 5;
            const float ah0 = (nu < 3) ? 1.f : 0.f;
            const float ah1 = (nu == 0) ? 0.f : ((nu == 1) ? 1.f : -1.f);
            const float aw0 = 1.f;
            const float aw1 = (mu == 0) ? 0.f : (mu == 1) ? 1.f : (mu == 2) ? -1.f
                            : (mu == 3) ? 2.f : -2.f;
            const float aw2 = (mu == 0) ? 0.f : (mu < 3) ? 1.f : 4.f;
            const float c00 = ah0 * aw0, c01 = ah0 * aw1, c02 = ah0 * aw2;
            const float c10 = ah1 * aw0, c11 = ah1 * aw1, c12 = ah1 * aw2;
            #pragma unroll
            for (int mt = 0; mt < 2; ++mt)
                #pragma unroll
                for (int nt = 0; nt < 2; ++nt)
                    #pragma unroll
                    for (int r = 0; r < 4; ++r) {
                        const float p = P[mt][nt][r];
                        o[0][mt][nt][r] += c00 * p;
                        o[1][mt][nt][r] += c01 * p;
                        o[2][mt][nt][r] += c02 * p;
                        o[3][mt][nt][r] += c10 * p;
                        o[4][mt][nt][r] += c11 * p;
                        o[5][mt][nt][r] += c12 * p;
                        P[mt][nt][r] = 0.f;
                    }
        }

        // issue stage for it+2
        if (it + 2 < 80) {
            const int jn  = it + 2;
            const int kt2 = jn & 3, xi2 = jn >> 2;
            int ns = cur + 2; if (ns >= 3) ns -= 3;
            const size_t offA = (size_t)xi2 * (F_ * C_) + kt2 * 64;
            const size_t offB = (size_t)xi2 * (NTP * C_) + kt2 * 64;
            #pragma unroll
            for (int q = 0; q < 4; ++q)
                cpa16(aD + ns * ASTG + q * 16, gA + offA + q * 8);
            cpa16(bD + ns * BSTG, gB + offB);
        }
        asm volatile("cp.async.commit_group;" ::: "memory");
        if (++cur == 3) cur = 0;
    }

    // ---- epilogue: 2x3 spatial per tile + bias ----
    float* ob = out + (size_t)b * HW * F_;
    const float* brow2 = g_beff + b * F_;
    #pragma unroll
    for (int mt = 0; mt < 2; ++mt) {
        #pragma unroll
        for (int nt = 0; nt < 2; ++nt) {
            #pragma unroll
            for (int r = 0; r < 4; ++r) {
                const int f = f0 + wm * 32 + mt * 16 + (lane >> 2) + ((r >> 1) << 3);
                const int tile = t0 + wn * 16 + nt * 8 + (lane & 3) * 2 + (r & 1);
                if (tile < NT) {
                    const int ti = tile / 19, tj = tile - (tile / 19) * 19;
                    const float bias = brow2[f];
                    #pragma unroll
                    for (int i = 0; i < 2; ++i) {
                        const int h = 2 * ti + i;
                        #pragma unroll
                        for (int j = 0; j < 3; ++j) {
                            const int w = 3 * tj + j;
                            if (w < 56)
                                ob[(size_t)(h * 56 + w) * F_ + f] = o[i * 3 + j][mt][nt][r] + bias;
                        }
                    }
                }
            }
        }
    }
}

// ============ launch ============
extern "C" void kernel_launch(void* const* d_in, const int* in_sizes, int n_in,
                              void* d_out, int out_size) {
    const float* x       = (const float*)d_in[0];
    const float* kernels = (const float*)d_in[1];
    const float* biases  = (const float*)d_in[2];
    const float* w1      = (const float*)d_in[3];
    const float* b1      = (const float*)d_in[4];
    const float* w2      = (const float*)d_in[5];
    const float* b2      = (const float*)d_in[6];
    float* out = (float*)d_out;

    // idempotent, capture-safe (no stream op, no allocation)
    cudaFuncSetAttribute(wino_gemm, cudaFuncAttributeMaxDynamicSharedMemorySize, SMEM_GEMM);

    itrans_kernel<<<dim3(16, 8, B_), 256>>>(x);
    router_kernel<<<B_, 256>>>(w1, b1, w2, b2, biases);
    wtrans_kernel<<<dim3(32, 8), 256>>>(kernels);
    wino_gemm<<<dim3(17, 2, B_), 256, SMEM_GEMM>>>(out);
}

// round 13
// speedup vs baseline: 1.1684x; 1.1684x over previous
#include <cuda_runtime.h>
#include <cuda_fp16.h>
#include <cstdint>

#define B_  32
#define HW  3136
#define C_  256
#define F_  256
#define NK  4
#define PER_B (2304*256)
#define NT  532            // 28(h) x 19(w) F(2x3) tiles per sample
#define NTP 544            // padded (17 blocks of 32); pad stays zero
#define XI  20             // 4(h) x 5(w)
#define PH  72             // gemm smem pitch in halves (64 + 8 pad)
#define ASTG (64*PH*2)     // 9216 B per A stage
#define BSTG (32*PH*2)     // 4608 B per B stage

// ---------------- scratch ----------------
__device__ float g_part[B_ * 16 * C_];
__device__ float g_attn[B_ * NK];
__device__ float g_beff[B_ * F_];
__device__ __half g_U[(size_t)B_ * XI * F_ * C_];    // [b][xi][f][c]
__device__ __half g_V[(size_t)B_ * XI * NTP * C_];   // [b][xi][tile][c] (pad zero)

// ============ 1) Input transform F(2x3) + fused GAP partial ============
__global__ void __launch_bounds__(256)
itrans_kernel(const float* __restrict__ x) {
    __shared__ float sx[16 * 17 * 32];
    __shared__ float red[8][32];
    const int b  = blockIdx.z;
    const int c0 = blockIdx.y * 32;
    const int bi = blockIdx.x >> 2, bj = blockIdx.x & 3;
    const int t  = threadIdx.x;

    const float* xb = x + (size_t)b * HW * C_ + c0;
    const int r0g = 14 * bi - 1, c0g = 15 * bj - 1;
    #pragma unroll
    for (int p = 0; p < 9; ++p) {
        int u = p * 256 + t;
        if (u < 2176) {
            int px = u >> 3, cu = u & 7;
            int rp = px / 17, cp = px - rp * 17;
            int ih = r0g + rp, iw = c0g + cp;
            float4 v = make_float4(0.f, 0.f, 0.f, 0.f);
            if ((unsigned)ih < 56u && (unsigned)iw < 56u)
                v = *(const float4*)(xb + (size_t)(ih * 56 + iw) * C_ + cu * 4);
            *(float4*)(sx + px * 32 + cu * 4) = v;
        }
    }
    __syncthreads();

    {
        const int part = t >> 5, cl = t & 31;
        float ps = 0.f;
        for (int i = part; i < 210; i += 8) {
            int rr = i / 15, cc = i - (i / 15) * 15;
            if (15 * bj + cc < 56)
                ps += sx[((rr + 1) * 17 + (cc + 1)) * 32 + cl];
        }
        red[part][cl] = ps;
    }
    __syncthreads();
    if (t < 32) {
        float s = 0.f;
        #pragma unroll
        for (int r = 0; r < 8; ++r) s += red[r][t];
        g_part[(b * 16 + blockIdx.x) * C_ + c0 + t] = s;
    }

    for (int item = t; item < 560; item += 256) {
        const int tile = item >> 4, cp2 = item & 15;
        const int lti = tile / 5, ltj = tile - (tile / 5) * 5;
        const int gti = 7 * bi + lti, gtj = 5 * bj + ltj;
        if (gtj >= 19) continue;
        const int cc = cp2 * 2;

        float2 d[4][5];
        #pragma unroll
        for (int i = 0; i < 4; ++i)
            #pragma unroll
            for (int j = 0; j < 5; ++j)
                d[i][j] = *(const float2*)(sx + ((2 * lti + i) * 17 + 3 * ltj + j) * 32 + cc);

        float2 T[4][5];
        #pragma unroll
        for (int j = 0; j < 5; ++j) {
            T[0][j] = make_float2(d[0][j].x - d[2][j].x, d[0][j].y - d[2][j].y);
            T[1][j] = make_float2(d[1][j].x + d[2][j].x, d[1][j].y + d[2][j].y);
            T[2][j] = make_float2(d[2][j].x - d[1][j].x, d[2][j].y - d[1][j].y);
            T[3][j] = make_float2(d[1][j].x - d[3][j].x, d[1][j].y - d[3][j].y);
        }

        const int tg = gti * 19 + gtj;
        __half* Vb = g_V + ((size_t)(b * XI) * NTP + tg) * C_ + c0 + cc;
        #pragma unroll
        for (int nu = 0; nu < 4; ++nu) {
            float2 t0 = T[nu][0], t1 = T[nu][1], t2 = T[nu][2], t3 = T[nu][3], t4 = T[nu][4];
            float2 V[5];
            V[0] = make_float2(4.f*t0.x - 5.f*t2.x + t4.x,      4.f*t0.y - 5.f*t2.y + t4.y);
            V[1] = make_float2(-4.f*t1.x - 4.f*t2.x + t3.x + t4.x, -4.f*t1.y - 4.f*t2.y + t3.y + t4.y);
            V[2] = make_float2(4.f*t1.x - 4.f*t2.x - t3.x + t4.x,  4.f*t1.y - 4.f*t2.y - t3.y + t4.y);
            V[3] = make_float2(-2.f*t1.x - t2.x + 2.f*t3.x + t4.x, -2.f*t1.y - t2.y + 2.f*t3.y + t4.y);
            V[4] = make_float2(2.f*t1.x - t2.x - 2.f*t3.x + t4.x,  2.f*t1.y - t2.y - 2.f*t3.y + t4.y);
            #pragma unroll
            for (int mu = 0; mu < 5; ++mu) {
                __half2 h = __floats2half2_rn(V[mu].x, V[mu].y);
                *(uint32_t*)(Vb + (size_t)(nu * 5 + mu) * NTP * C_) = *(uint32_t*)&h;
            }
        }
    }
}

// ============ 2) Fused: GAP final + router MLP + softmax + beff ============
__global__ void router_kernel(const float* __restrict__ w1, const float* __restrict__ b1,
                              const float* __restrict__ w2, const float* __restrict__ b2,
                              const float* __restrict__ biases) {
    int b = blockIdx.x, t = threadIdx.x;
    __shared__ float sp[C_];
    __shared__ float sh[64];
    __shared__ float sl[NK];
    __shared__ float sa[NK];
    float s = 0.f;
    #pragma unroll
    for (int ch = 0; ch < 16; ++ch) s += g_part[(b * 16 + ch) * C_ + t];
    sp[t] = s * (1.0f / 3136.0f);
    __syncthreads();
    if (t < 64) {
        float acc = b1[t];
        #pragma unroll 4
        for (int c = 0; c < C_; ++c) acc += sp[c] * w1[c * 64 + t];
        sh[t] = fmaxf(acc, 0.f);
    }
    __syncthreads();
    if (t < NK) {
        float lg = b2[t];
        #pragma unroll
        for (int i = 0; i < 64; ++i) lg += sh[i] * w2[i * NK + t];
        sl[t] = lg * (1.0f / 30.0f);
    }
    __syncthreads();
    if (t == 0) {
        float mx = fmaxf(fmaxf(sl[0], sl[1]), fmaxf(sl[2], sl[3]));
        float e0 = expf(sl[0] - mx), e1 = expf(sl[1] - mx);
        float e2 = expf(sl[2] - mx), e3 = expf(sl[3] - mx);
        float inv = 1.0f / (e0 + e1 + e2 + e3);
        sa[0] = e0 * inv; sa[1] = e1 * inv; sa[2] = e2 * inv; sa[3] = e3 * inv;
        g_attn[b * NK + 0] = sa[0]; g_attn[b * NK + 1] = sa[1];
        g_attn[b * NK + 2] = sa[2]; g_attn[b * NK + 3] = sa[3];
    }
    __syncthreads();
    float bs = 0.f;
    #pragma unroll
    for (int k = 0; k < NK; ++k) bs += sa[k] * biases[k * F_ + t];
    g_beff[b * F_ + t] = bs;
}

// ============ 3) Weight transform: U = Gh W Gw^T, fp16 [b][xi][f][c] ============
__global__ void __launch_bounds__(256)
wtrans_kernel(const float* __restrict__ kern) {
    __shared__ float sk[4][9][8][33];
    __shared__ float sa[B_][NK];
    const int f0 = blockIdx.x * 8;
    const int c0 = blockIdx.y * 32;
    const int t  = threadIdx.x;

    #pragma unroll
    for (int p = 0; p < 36; ++p) {
        int i  = p * 256 + t;
        int fl = i & 7, cl = (i >> 3) & 31, rs = (i >> 8) % 9, k = i / 2304;
        sk[k][rs][fl][cl] =
            kern[(size_t)k * PER_B + (size_t)rs * (C_ * F_) + (size_t)(c0 + cl) * F_ + f0 + fl];
    }
    if (t < B_ * NK) sa[t >> 2][t & 3] = g_attn[t];
    __syncthreads();

    const int fl = t >> 5, cl = t & 31;
    const float S6 = 1.f / 6.f, S24 = 1.f / 24.f;
    #pragma unroll 1
    for (int b = 0; b < B_; ++b) {
        const float a0 = sa[b][0], a1 = sa[b][1], a2 = sa[b][2], a3 = sa[b][3];
        float g[3][3];
        #pragma unroll
        for (int rs = 0; rs < 9; ++rs)
            g[rs / 3][rs % 3] = a0 * sk[0][rs][fl][cl] + a1 * sk[1][rs][fl][cl]
                              + a2 * sk[2][rs][fl][cl] + a3 * sk[3][rs][fl][cl];
        float q[4][3];
        #pragma unroll
        for (int j = 0; j < 3; ++j) {
            q[0][j] = g[0][j];
            q[1][j] = 0.5f * (g[0][j] + g[1][j] + g[2][j]);
            q[2][j] = 0.5f * (g[0][j] - g[1][j] + g[2][j]);
            q[3][j] = g[2][j];
        }
        __half* Ub = g_U + ((size_t)(b * XI) * F_ + f0 + fl) * C_ + c0 + cl;
        #pragma unroll
        for (int i = 0; i < 4; ++i) {
            float u0 = 0.25f * q[i][0];
            float u1 = -S6 * (q[i][0] + q[i][1] + q[i][2]);
            float u2 = -S6 * (q[i][0] - q[i][1] + q[i][2]);
            float u3 = S24 * (q[i][0] + 2.f * q[i][1] + 4.f * q[i][2]);
            float u4 = S24 * (q[i][0] - 2.f * q[i][1] + 4.f * q[i][2]);
            Ub[(size_t)(i * 5 + 0) * (F_ * C_)] = __float2half(u0);
            Ub[(size_t)(i * 5 + 1) * (F_ * C_)] = __float2half(u1);
            Ub[(size_t)(i * 5 + 2) * (F_ * C_)] = __float2half(u2);
            Ub[(size_t)(i * 5 + 3) * (F_ * C_)] = __float2half(u3);
            Ub[(size_t)(i * 5 + 4) * (F_ * C_)] = __float2half(u4);
        }
    }
}

// ============ 4) Fused Winograd GEMM + inverse transform ============
// CTA 64f x 32t x BK=64, 3-stage cp.async, 2 CTAs/SM.
// 8 warps (4m x 2n): warp = 16f x 16t -> 8 MMA / 8 LDSM per iter. 80 iters.
__device__ __forceinline__ void ldm_x4(uint32_t* r, uint32_t addr) {
    asm volatile("ldmatrix.sync.aligned.m8n8.x4.shared.b16 {%0,%1,%2,%3}, [%4];"
        : "=r"(r[0]), "=r"(r[1]), "=r"(r[2]), "=r"(r[3]) : "r"(addr));
}
__device__ __forceinline__ void mma_f16(float* d, const uint32_t* a, const uint32_t* bb) {
    asm volatile(
        "mma.sync.aligned.m16n8k16.row.col.f32.f16.f16.f32 "
        "{%0,%1,%2,%3},{%4,%5,%6,%7},{%8,%9},{%0,%1,%2,%3};"
        : "+f"(d[0]), "+f"(d[1]), "+f"(d[2]), "+f"(d[3])
        : "r"(a[0]), "r"(a[1]), "r"(a[2]), "r"(a[3]), "r"(bb[0]), "r"(bb[1]));
}
__device__ __forceinline__ void cpa16(uint32_t s, const void* g) {
    asm volatile("cp.async.ca.shared.global [%0], [%1], 16;" :: "r"(s), "l"(g) : "memory");
}

__global__ void __launch_bounds__(256, 2)
wino_gemm(float* __restrict__ out) {
    __shared__ __align__(16) __half As[3][64][PH];
    __shared__ __align__(16) __half Bs[3][32][PH];

    const int t    = threadIdx.x;
    const int lane = t & 31;
    const int warp = t >> 5;
    const int wm   = warp >> 1;          // 0..3 : 16 f each
    const int wn   = warp & 1;           // 0..1 : 16 tiles each
    const int b    = blockIdx.z;
    const int f0   = blockIdx.y * 64;
    const int t0   = blockIdx.x * 32;

    const __half* Ub = g_U + (size_t)b * XI * F_ * C_;
    const __half* Vb = g_V + (size_t)b * XI * NTP * C_;

    const uint32_t aSm = (uint32_t)__cvta_generic_to_shared(&As[0][0][0]);
    const uint32_t bSm = (uint32_t)__cvta_generic_to_shared(&Bs[0][0][0]);
    // ldmatrix lane addresses (stage 0)
    const uint32_t aLm = aSm + (uint32_t)(((wm * 16 + (lane & 15)) * PH + (lane >> 4) * 8) * 2);
    const uint32_t bLm = bSm + (uint32_t)(((wn * 16 + (lane & 7) + ((lane >> 4) & 1) * 8) * PH
                                           + ((lane >> 3) & 1) * 8) * 2);
    // loaders: A 64 rows x 8 chunks (2/thread), B 32 rows x 8 chunks (1/thread)
    const int arow = t >> 2;
    const int acol = (t & 3) * 16;       // halves
    const int brow = t >> 3;
    const int bcol = (t & 7) * 8;
    const uint32_t aD = aSm + (uint32_t)((arow * PH + acol) * 2);
    const uint32_t bD = bSm + (uint32_t)((brow * PH + bcol) * 2);
    const __half* gA = Ub + (size_t)(f0 + arow) * C_ + acol;
    const __half* gB = Vb + (size_t)(t0 + brow) * C_ + bcol;

    float P[2][4];          // [nt][reg]
    float o[6][2][4];       // [i*3+j][nt][reg]
    #pragma unroll
    for (int nt = 0; nt < 2; ++nt)
        #pragma unroll
        for (int r = 0; r < 4; ++r) P[nt][r] = 0.f;
    #pragma unroll
    for (int ij = 0; ij < 6; ++ij)
        #pragma unroll
        for (int nt = 0; nt < 2; ++nt)
            #pragma unroll
            for (int r = 0; r < 4; ++r) o[ij][nt][r] = 0.f;

    // prologue: stages 0,1 <- it 0,1 (xi=0, kt=0,1)
    #pragma unroll
    for (int j = 0; j < 2; ++j) {
        cpa16(aD + j * ASTG,      gA + j * 64);
        cpa16(aD + j * ASTG + 16, gA + j * 64 + 8);
        cpa16(bD + j * BSTG,      gB + j * 64);
        asm volatile("cp.async.commit_group;" ::: "memory");
    }

    int cur = 0;
    #pragma unroll 1
    for (int it = 0; it < 80; ++it) {
        asm volatile("cp.async.wait_group 1;" ::: "memory");
        __syncthreads();

        const uint32_t soA = (uint32_t)(cur * ASTG);
        const uint32_t soB = (uint32_t)(cur * BSTG);
        uint32_t bf[4][4];
        #pragma unroll
        for (int ks = 0; ks < 4; ++ks)
            ldm_x4(bf[ks], bLm + soB + ks * 32);
        #pragma unroll
        for (int ks = 0; ks < 4; ++ks) {
            uint32_t afr[4];
            ldm_x4(afr, aLm + soA + ks * 32);
            mma_f16(P[0], afr, &bf[ks][0]);
            mma_f16(P[1], afr, &bf[ks][2]);
        }

        // fold xi into inverse-transform accumulators
        if ((it & 3) == 3) {
            const int xi = it >> 2;
            const int nu = xi / 5, mu = xi - nu * 5;
            const float ah0 = (nu < 3) ? 1.f : 0.f;
            const float ah1 = (nu == 0) ? 0.f : ((nu == 1) ? 1.f : -1.f);
            const float aw0 = 1.f;
            const float aw1 = (mu == 0) ? 0.f : (mu == 1) ? 1.f : (mu == 2) ? -1.f
                            : (mu == 3) ? 2.f : -2.f;
            const float aw2 = (mu == 0) ? 0.f : (mu < 3) ? 1.f : 4.f;
            const float c00 = ah0 * aw0, c01 = ah0 * aw1, c02 = ah0 * aw2;
            const float c10 = ah1 * aw0, c11 = ah1 * aw1, c12 = ah1 * aw2;
            #pragma unroll
            for (int nt = 0; nt < 2; ++nt)
                #pragma unroll
                for (int r = 0; r < 4; ++r) {
                    const float p = P[nt][r];
                    o[0][nt][r] += c00 * p;
                    o[1][nt][r] += c01 * p;
                    o[2][nt][r] += c02 * p;
                    o[3][nt][r] += c10 * p;
                    o[4][nt][r] += c11 * p;
                    o[5][nt][r] += c12 * p;
                    P[nt][r] = 0.f;
                }
        }

        // issue stage for it+2
        if (it + 2 < 80) {
            const int jn  = it + 2;
            const int kt2 = jn & 3, xi2 = jn >> 2;
            int ns = cur + 2; if (ns >= 3) ns -= 3;
            const size_t offA = (size_t)xi2 * (F_ * C_) + kt2 * 64;
            const size_t offB = (size_t)xi2 * (NTP * C_) + kt2 * 64;
            cpa16(aD + ns * ASTG,      gA + offA);
            cpa16(aD + ns * ASTG + 16, gA + offA + 8);
            cpa16(bD + ns * BSTG,      gB + offB);
        }
        asm volatile("cp.async.commit_group;" ::: "memory");
        if (++cur == 3) cur = 0;
    }

    // ---- epilogue: 2x3 spatial per tile + bias ----
    float* ob = out + (size_t)b * HW * F_;
    const float* brow2 = g_beff + b * F_;
    #pragma unroll
    for (int nt = 0; nt < 2; ++nt) {
        #pragma unroll
        for (int r = 0; r < 4; ++r) {
            const int f = f0 + wm * 16 + (lane >> 2) + ((r >> 1) << 3);
            const int tile = t0 + wn * 16 + nt * 8 + (lane & 3) * 2 + (r & 1);
            if (tile < NT) {
                const int ti = tile / 19, tj = tile - (tile / 19) * 19;
                const float bias = brow2[f];
                #pragma unroll
                for (int i = 0; i < 2; ++i) {
                    const int h = 2 * ti + i;
                    #pragma unroll
                    for (int j = 0; j < 3; ++j) {
                        const int w = 3 * tj + j;
                        if (w < 56)
                            ob[(size_t)(h * 56 + w) * F_ + f] = o[i * 3 + j][nt][r] + bias;
                    }
                }
            }
        }
    }
}

// ============ launch ============
extern "C" void kernel_launch(void* const* d_in, const int* in_sizes, int n_in,
                              void* d_out, int out_size) {
    const float* x       = (const float*)d_in[0];
    const float* kernels = (const float*)d_in[1];
    const float* biases  = (const float*)d_in[2];
    const float* w1      = (const float*)d_in[3];
    const float* b1      = (const float*)d_in[4];
    const float* w2      = (const float*)d_in[5];
    const float* b2      = (const float*)d_in[6];
    float* out = (float*)d_out;

    itrans_kernel<<<dim3(16, 8, B_), 256>>>(x);
    router_kernel<<<B_, 256>>>(w1, b1, w2, b2, biases);
    wtrans_kernel<<<dim3(32, 8), 256>>>(kernels);
    wino_gemm<<<dim3(17, 4, B_), 256>>>(out);
}